// round 1
// baseline (speedup 1.0000x reference)
#include <cuda_runtime.h>
#include <math.h>

#define D 256
#define H 128
#define BN 16
#define GAMMA   (-0.5f)
#define ZETA    (1.1f)
#define DBGVAR  (1e-7f)

// scratch (allocation-free rule: __device__ globals)
__device__ float g_snb[65536];
__device__ float g_sself[65536];
__device__ float g_rowsum[65536];
__device__ float g_mv[1 << 20];

// ---------------------------------------------------------------------------
// Kernel 1: per-node attention scores + rowsum zero-init
//   s_nb[n]   = relu(x[n] @ W_nb   + b_nb)   . W_att[0:H]
//   s_self[n] = relu(x[n] @ W_self + b_self) . W_att[H:2H]
// One block handles BN=16 nodes; 128 threads = one h-column each.
// ---------------------------------------------------------------------------
__global__ __launch_bounds__(128)
void node_scores_kernel(const float* __restrict__ x,
                        const float* __restrict__ Wnb,
                        const float* __restrict__ bnb,
                        const float* __restrict__ Wself,
                        const float* __restrict__ bself,
                        const float* __restrict__ Watt,
                        int N)
{
    __shared__ float xs[BN * D];            // 16 KB
    __shared__ float red_nb[4][BN];         // per-warp partials
    __shared__ float red_self[4][BN];

    const int t     = threadIdx.x;          // 0..127 (h index)
    const int warp  = t >> 5;
    const int lane  = t & 31;
    const int node0 = blockIdx.x * BN;

    // zero rowsum: grid covers >= N threads (blocks = ceil(N/16), x128 = 8N)
    int gid = blockIdx.x * blockDim.x + t;
    if (gid < N) g_rowsum[gid] = 0.0f;

    // load x tile into smem (coalesced)
    for (int i = t; i < BN * D; i += 128) {
        int j = i >> 8;          // i / D
        int d = i & (D - 1);     // i % D
        int n = node0 + j;
        xs[i] = (n < N) ? x[n * D + d] : 0.0f;
    }
    __syncthreads();

    float acc_nb[BN], acc_self[BN];
#pragma unroll
    for (int j = 0; j < BN; j++) { acc_nb[j] = 0.0f; acc_self[j] = 0.0f; }

    // mainloop: d in chunks of 4, W column loads hit L2 (W is 256 KB total)
    for (int d0 = 0; d0 < D; d0 += 4) {
        float wn0 = Wnb[(d0 + 0) * H + t];
        float wn1 = Wnb[(d0 + 1) * H + t];
        float wn2 = Wnb[(d0 + 2) * H + t];
        float wn3 = Wnb[(d0 + 3) * H + t];
        float ws0 = Wself[(d0 + 0) * H + t];
        float ws1 = Wself[(d0 + 1) * H + t];
        float ws2 = Wself[(d0 + 2) * H + t];
        float ws3 = Wself[(d0 + 3) * H + t];
#pragma unroll
        for (int j = 0; j < BN; j++) {
            float4 xv = *reinterpret_cast<const float4*>(&xs[j * D + d0]);
            acc_nb[j]   = fmaf(xv.x, wn0, acc_nb[j]);
            acc_nb[j]   = fmaf(xv.y, wn1, acc_nb[j]);
            acc_nb[j]   = fmaf(xv.z, wn2, acc_nb[j]);
            acc_nb[j]   = fmaf(xv.w, wn3, acc_nb[j]);
            acc_self[j] = fmaf(xv.x, ws0, acc_self[j]);
            acc_self[j] = fmaf(xv.y, ws1, acc_self[j]);
            acc_self[j] = fmaf(xv.z, ws2, acc_self[j]);
            acc_self[j] = fmaf(xv.w, ws3, acc_self[j]);
        }
    }

    // epilogue: relu, weight by w_att, reduce over the 128 h-columns
    const float bn = bnb[t];
    const float bs = bself[t];
    const float w1 = Watt[t];
    const float w2 = Watt[H + t];

#pragma unroll
    for (int j = 0; j < BN; j++) {
        float v1 = fmaxf(acc_nb[j]   + bn, 0.0f) * w1;
        float v2 = fmaxf(acc_self[j] + bs, 0.0f) * w2;
#pragma unroll
        for (int off = 16; off > 0; off >>= 1) {
            v1 += __shfl_down_sync(0xffffffff, v1, off);
            v2 += __shfl_down_sync(0xffffffff, v2, off);
        }
        if (lane == 0) {
            red_nb[warp][j]   = v1;
            red_self[warp][j] = v2;
        }
    }
    __syncthreads();

    if (t < BN && node0 + t < N) {
        float s1 = red_nb[0][t] + red_nb[1][t] + red_nb[2][t] + red_nb[3][t];
        float s2 = red_self[0][t] + red_self[1][t] + red_self[2][t] + red_self[3][t];
        g_snb[node0 + t]   = s1;
        g_sself[node0 + t] = s2;
    }
}

// ---------------------------------------------------------------------------
// Kernel 2: per-edge mask + masked value + rowsum scatter
// ---------------------------------------------------------------------------
__global__ __launch_bounds__(256)
void edge_mask_kernel(const float* __restrict__ values,
                      const float* __restrict__ noise,
                      const int*   __restrict__ row,
                      const int*   __restrict__ col,
                      const float* __restrict__ batt,
                      int E)
{
    int e = blockIdx.x * blockDim.x + threadIdx.x;
    if (e >= E) return;

    int r = row[e];
    int c = col[e];
    float la = g_snb[r] + g_sself[c] + batt[0];

    float u = noise[e] + DBGVAR;
    float z = logf(u) - logf(1.0f - u) + la;
    float gate = 1.0f / (1.0f + expf(-z));
    float mask = fminf(fmaxf(gate * (ZETA - GAMMA) + GAMMA, 0.0f), 1.0f);
    float mv = values[e] * mask;

    g_mv[e] = mv;
    if (mv != 0.0f) atomicAdd(&g_rowsum[r], mv);
}

// ---------------------------------------------------------------------------
// Kernel 3: degree normalization
// ---------------------------------------------------------------------------
__global__ __launch_bounds__(256)
void edge_norm_kernel(const int* __restrict__ row,
                      const int* __restrict__ col,
                      float* __restrict__ out,
                      int E)
{
    int e = blockIdx.x * blockDim.x + threadIdx.x;
    if (e >= E) return;

    float mv = g_mv[e];
    float dr = 1.0f / sqrtf(g_rowsum[row[e]] + 1e-10f);
    float dc = 1.0f / sqrtf(g_rowsum[col[e]] + 1e-10f);
    out[e] = mv * dr * dc;
}

// ---------------------------------------------------------------------------
extern "C" void kernel_launch(void* const* d_in, const int* in_sizes, int n_in,
                              void* d_out, int out_size)
{
    const float* x      = (const float*)d_in[0];
    const float* Wnb    = (const float*)d_in[1];
    const float* bnb    = (const float*)d_in[2];
    const float* Wself  = (const float*)d_in[3];
    const float* bself  = (const float*)d_in[4];
    const float* Watt   = (const float*)d_in[5];
    const float* batt   = (const float*)d_in[6];
    const float* values = (const float*)d_in[7];
    const float* noise  = (const float*)d_in[8];
    const int*   row    = (const int*)d_in[9];
    const int*   col    = (const int*)d_in[10];
    float* out = (float*)d_out;

    int N = in_sizes[0] / D;     // 50000
    int E = in_sizes[7];         // 800000

    int nodeBlocks = (N + BN - 1) / BN;
    node_scores_kernel<<<nodeBlocks, 128>>>(x, Wnb, bnb, Wself, bself, Watt, N);

    int edgeBlocks = (E + 255) / 256;
    edge_mask_kernel<<<edgeBlocks, 256>>>(values, noise, row, col, batt, E);
    edge_norm_kernel<<<edgeBlocks, 256>>>(row, col, out, E);
}